// round 3
// baseline (speedup 1.0000x reference)
#include <cuda_runtime.h>
#include <math.h>

// ---- problem constants ----
#define HD   128
#define HQ   32
#define HKV  8
#define SQC  4096
#define SKVC 4096
#define BQ   128
#define BKV  128
#define WIN  512
#define CAPV 50.0f
#define EPSV 1e-5f

#define PITCH  129   // smem row pitch (floats): 129 mod 32 = 1 -> conflict-free row starts
#define RPITCH 17    // reduction buffer pitch: conflict-free column walks

__device__ __forceinline__ float warp_sum(float v) {
    #pragma unroll
    for (int o = 16; o; o >>= 1) v += __shfl_xor_sync(0xffffffffu, v, o);
    return v;
}

__global__ __launch_bounds__(256, 1)
void oswa_kernel(const float* __restrict__ q, const float* __restrict__ k,
                 const float* __restrict__ v, const float* __restrict__ g_o,
                 const float* __restrict__ g_lse, const float* __restrict__ gq,
                 const float* __restrict__ gk, const int* __restrict__ p_biq,
                 const int* __restrict__ p_bikv,
                 float* __restrict__ out_o, float* __restrict__ out_lse)
{
    extern __shared__ float sm[];
    float* sQ  = sm;                    // [BQ][PITCH] normalized Q; later reused as P
    float* sKT = sm + BQ * PITCH;       // [HD][PITCH] normalized K^T; later reused as red[BQ][RPITCH]
    float* sV  = sm + 2 * BQ * PITCH;   // [BKV][PITCH] V

    __shared__ float rowmax_s[BQ];
    __shared__ float co_s[BQ];
    __shared__ float cb_s[BQ];

    const int bh  = blockIdx.x;
    const int b   = bh / HQ;
    const int h   = bh % HQ;
    const int kvh = h / (HQ / HKV);
    const int biq  = __ldg(p_biq);
    const int bikv = __ldg(p_bikv);

    const int tid  = threadIdx.x;
    const int lane = tid & 31;
    const int warp = tid >> 5;

    const float scale = 0.08838834764831845f;  // 1/sqrt(128)

    // ---------- load + RMS-norm Q,K (gamma per channel); load V ----------
    {
        const float4 gqv = ((const float4*)(gq + (size_t)h * HD))[lane];
        const float4 gkv = ((const float4*)(gk + (size_t)kvh * HD))[lane];
        for (int r = warp * 16; r < warp * 16 + 16; ++r) {
            // Q row
            float4 x = ((const float4*)(q + ((size_t)(b * BQ + r) * HQ + h) * HD))[lane];
            float ssq = warp_sum(x.x * x.x + x.y * x.y + x.z * x.z + x.w * x.w);
            float riq = rsqrtf(ssq * (1.0f / HD) + EPSV);
            float* dq = sQ + r * PITCH + lane * 4;
            dq[0] = x.x * riq * gqv.x; dq[1] = x.y * riq * gqv.y;
            dq[2] = x.z * riq * gqv.z; dq[3] = x.w * riq * gqv.w;
            // K row -> transposed store
            float4 y = ((const float4*)(k + ((size_t)(b * BKV + r) * HKV + kvh) * HD))[lane];
            float ssk = warp_sum(y.x * y.x + y.y * y.y + y.z * y.z + y.w * y.w);
            float rik = rsqrtf(ssk * (1.0f / HD) + EPSV);
            const int d0 = lane * 4;
            sKT[(d0 + 0) * PITCH + r] = y.x * rik * gkv.x;
            sKT[(d0 + 1) * PITCH + r] = y.y * rik * gkv.y;
            sKT[(d0 + 2) * PITCH + r] = y.z * rik * gkv.z;
            sKT[(d0 + 3) * PITCH + r] = y.w * rik * gkv.w;
            // V row
            float4 z = ((const float4*)(v + ((size_t)(b * BKV + r) * HKV + kvh) * HD))[lane];
            float* dv = sV + r * PITCH + lane * 4;
            dv[0] = z.x; dv[1] = z.y; dv[2] = z.z; dv[3] = z.w;
        }
    }
    __syncthreads();

    // thread tile: 8x8 of the 128x128 score matrix
    const int tr = tid >> 4;  // 0..15
    const int tc = tid & 15;  // 0..15
    const int r0 = tr * 8;
    const int c0 = tc * 8;

    // ---------- GEMM1: S = Qn @ Kn^T ----------
    float acc[8][8];
    #pragma unroll
    for (int i = 0; i < 8; ++i)
        #pragma unroll
        for (int j = 0; j < 8; ++j) acc[i][j] = 0.0f;

    for (int d = 0; d < HD; ++d) {
        float a[8], bb[8];
        #pragma unroll
        for (int i = 0; i < 8; ++i) a[i] = sQ[(r0 + i) * PITCH + d];
        #pragma unroll
        for (int j = 0; j < 8; ++j) bb[j] = sKT[d * PITCH + c0 + j];
        #pragma unroll
        for (int i = 0; i < 8; ++i)
            #pragma unroll
            for (int j = 0; j < 8; ++j) acc[i][j] = fmaf(a[i], bb[j], acc[i][j]);
    }
    __syncthreads();  // done reading sQ / sKT contents

    // ---------- scale + tanh cap + mask + row max ----------
    float* red = sKT;  // reuse as [BQ][RPITCH]
    const int qbase = biq * BQ;
    const int kbase = bikv * BKV;
    const int offs  = SKVC - SQC;
    #pragma unroll
    for (int i = 0; i < 8; ++i) {
        const int qi = qbase + r0 + i;
        float m = -INFINITY;
        #pragma unroll
        for (int j = 0; j < 8; ++j) {
            const int kj = kbase + c0 + j;
            float s = acc[i][j] * scale;
            s = CAPV * tanhf(s * (1.0f / CAPV));
            const bool allowed = (kj <= qi + offs) && (kj >= qi + offs - WIN) &&
                                 (qi < SQC) && (kj < SKVC);
            s = allowed ? s : -INFINITY;
            acc[i][j] = s;
            m = fmaxf(m, s);
        }
        red[(r0 + i) * RPITCH + tc] = m;
    }
    __syncthreads();
    if (tid < BQ) {
        float m = -INFINITY;
        #pragma unroll
        for (int t = 0; t < 16; ++t) m = fmaxf(m, red[tid * RPITCH + t]);
        rowmax_s[tid] = m;
    }
    __syncthreads();

    // ---------- exp (unnormalized), write P, partial sums ----------
    float* sP = sQ;
    #pragma unroll
    for (int i = 0; i < 8; ++i) {
        const float m = rowmax_s[r0 + i];
        float s = 0.0f;
        #pragma unroll
        for (int j = 0; j < 8; ++j) {
            float pv = (m == -INFINITY) ? 0.0f : expf(acc[i][j] - m);
            sP[(r0 + i) * PITCH + c0 + j] = pv;
            s += pv;
        }
        red[(r0 + i) * RPITCH + tc] = s;
    }
    __syncthreads();

    // ---------- per-row: lse_blk, online merge coefficients, lse write ----------
    if (tid < BQ) {
        float s = 0.0f;
        #pragma unroll
        for (int t = 0; t < 16; ++t) s += red[tid * RPITCH + t];
        const float m = rowmax_s[tid];
        const float lse_blk = (s > 0.0f && m > -INFINITY) ? (m + logf(s)) : -INFINITY;

        const int grow = qbase + tid;
        const float lo = g_lse[((size_t)b * HQ + h) * SQC + grow];
        const float m2 = fmaxf(lo, lse_blk);
        float lnew, co, cb;
        if (m2 == -INFINITY) {
            lnew = -INFINITY; co = 0.0f; cb = 0.0f;
        } else {
            float e0 = (lo == -INFINITY) ? 0.0f : expf(lo - m2);
            float e1 = (lse_blk == -INFINITY) ? 0.0f : expf(lse_blk - m2);
            lnew = m2 + logf(e0 + e1);
            co = (lo == -INFINITY) ? 0.0f : expf(lo - lnew);
            cb = (lse_blk == -INFINITY) ? 0.0f : expf(lse_blk - lnew);
        }
        co_s[tid] = co;
        cb_s[tid] = (s > 0.0f) ? (cb / s) : 0.0f;  // fold 1/rowsum into the block coeff
        out_lse[((size_t)b * HQ + h) * SQC + grow] = lnew;
    }
    __syncthreads();

    // ---------- GEMM2: O_blk_unnorm = P @ V ----------
    float acc2[8][8];
    #pragma unroll
    for (int i = 0; i < 8; ++i)
        #pragma unroll
        for (int j = 0; j < 8; ++j) acc2[i][j] = 0.0f;

    for (int kk = 0; kk < BKV; ++kk) {
        float a[8], bb[8];
        #pragma unroll
        for (int i = 0; i < 8; ++i) a[i] = sP[(r0 + i) * PITCH + kk];
        #pragma unroll
        for (int j = 0; j < 8; ++j) bb[j] = sV[kk * PITCH + c0 + j];
        #pragma unroll
        for (int i = 0; i < 8; ++i)
            #pragma unroll
            for (int j = 0; j < 8; ++j) acc2[i][j] = fmaf(a[i], bb[j], acc2[i][j]);
    }

    // ---------- merge with old global O and write ----------
    #pragma unroll
    for (int i = 0; i < 8; ++i) {
        const int r = r0 + i;
        const int grow = qbase + r;
        const size_t base = (((size_t)b * SQC + grow) * HQ + h) * HD;
        const float co = co_s[r];
        const float cb = cb_s[r];
        #pragma unroll
        for (int j = 0; j < 8; ++j) {
            const int c = c0 + j;
            out_o[base + c] = co * g_o[base + c] + cb * acc2[i][j];
        }
    }
}

extern "C" void kernel_launch(void* const* d_in, const int* in_sizes, int n_in,
                              void* d_out, int out_size)
{
    const float* q     = (const float*)d_in[0];
    const float* k     = (const float*)d_in[1];
    const float* v     = (const float*)d_in[2];
    const float* g_o   = (const float*)d_in[3];
    const float* g_lse = (const float*)d_in[4];
    const float* gq    = (const float*)d_in[5];
    const float* gk    = (const float*)d_in[6];
    const int*   biq   = (const int*)d_in[7];
    const int*   bikv  = (const int*)d_in[8];

    float* out = (float*)d_out;

    const int    b_dim     = in_sizes[0] / (BQ * HQ * HD);          // 4
    const size_t o_elems   = (size_t)in_sizes[3];                   // b*SQ*HQ*HD
    const size_t lse_elems = (size_t)in_sizes[4];                   // b*HQ*SQ

    // Bulk-copy the unmodified global tensors into the output (near-peak HBM).
    cudaMemcpyAsync(out, g_o, o_elems * sizeof(float),
                    cudaMemcpyDeviceToDevice, 0);
    cudaMemcpyAsync(out + o_elems, g_lse, lse_elems * sizeof(float),
                    cudaMemcpyDeviceToDevice, 0);

    const size_t smem = (size_t)3 * BQ * PITCH * sizeof(float);  // 198144 B
    cudaFuncSetAttribute(oswa_kernel,
                         cudaFuncAttributeMaxDynamicSharedMemorySize, (int)smem);

    // One CTA per (batch, q-head); overwrites the updated 128-row block region.
    oswa_kernel<<<b_dim * HQ, 256, smem, 0>>>(
        q, k, v, g_o, g_lse, gq, gk, biq, bikv, out, out + o_elems);
}

// round 4
// speedup vs baseline: 1.0862x; 1.0862x over previous
#include <cuda_runtime.h>
#include <math.h>

// ---- problem constants ----
#define HD   128
#define HQ   32
#define HKV  8
#define SQC  4096
#define SKVC 4096
#define BQ   128
#define BKV  128
#define WIN  512
#define CAPV 50.0f
#define EPSV 1e-5f

#define PITCH  132   // smem row pitch in floats; multiple of 4 -> float4-aligned rows
#define RPITCH 17    // reduction buffer pitch
#define NCOPY  1024  // copy CTAs

__device__ __forceinline__ float warp_sum(float v) {
    #pragma unroll
    for (int o = 16; o; o >>= 1) v += __shfl_xor_sync(0xffffffffu, v, o);
    return v;
}

__global__ __launch_bounds__(256, 1)
void oswa_fused(const float* __restrict__ q, const float* __restrict__ k,
                const float* __restrict__ v, const float* __restrict__ g_o,
                const float* __restrict__ g_lse, const float* __restrict__ gq,
                const float* __restrict__ gk, const int* __restrict__ p_biq,
                const int* __restrict__ p_bikv,
                float* __restrict__ out_o, float* __restrict__ out_lse,
                int natt, unsigned long long o_elems, unsigned long long lse_elems)
{
    const int tid = threadIdx.x;

    // =====================  COPY BRANCH  =====================
    if ((int)blockIdx.x >= natt) {
        const int cid = blockIdx.x - natt;
        const unsigned qbase = (unsigned)(__ldg(p_biq) * BQ);

        // ---- global_o: grid-stride float4 copy, skipping the block rows ----
        const float4* __restrict__ src = (const float4*)g_o;
        float4* __restrict__ dst = (float4*)out_o;
        const size_t n4 = (size_t)(o_elems >> 2);
        const size_t stride = (size_t)NCOPY * 1024;           // 256 thr * 4 per iter
        for (size_t i = (size_t)cid * 1024 + tid; i < n4; i += stride) {
            float4 r[4]; bool ok[4];
            #pragma unroll
            for (int u = 0; u < 4; ++u) {
                size_t ii = i + (size_t)u * 256;
                ok[u] = (ii < n4);
                if (ok[u]) {
                    unsigned row = (unsigned)(ii >> 10);       // 1024 float4 per seq row
                    unsigned s   = row & (SQC - 1);
                    if ((s - qbase) < (unsigned)BQ) ok[u] = false;   // block region -> attention writes it
                    else r[u] = src[ii];
                }
            }
            #pragma unroll
            for (int u = 0; u < 4; ++u)
                if (ok[u]) dst[i + (size_t)u * 256] = r[u];
        }

        // ---- global_lse: skip the block columns ----
        const float4* __restrict__ srcl = (const float4*)g_lse;
        float4* __restrict__ dstl = (float4*)out_lse;
        const size_t n4l = (size_t)(lse_elems >> 2);
        const unsigned qb4 = qbase >> 2;
        for (size_t j = (size_t)cid * 256 + tid; j < n4l; j += (size_t)NCOPY * 256) {
            unsigned col = (unsigned)j & 1023u;                // 1024 float4 per (b,h) row
            if ((col - qb4) < 32u) continue;
            dstl[j] = srcl[j];
        }
        return;
    }

    // =====================  ATTENTION BRANCH  =====================
    extern __shared__ float sm[];
    float* sQ = sm;                      // [128][132] normalized Q; later reused as P
    float* sK = sm + BQ * PITCH;         // [128][132] normalized K (row-rotated chunks); later red[]
    float* sV = sm + 2 * BQ * PITCH;     // [128][132] V (interleaved chunks)

    __shared__ float rowmax_s[BQ];
    __shared__ float co_s[BQ];
    __shared__ float cb_s[BQ];

    const int bh  = blockIdx.x;
    const int b   = bh >> 5;
    const int h   = bh & 31;
    const int kvh = h / (HQ / HKV);
    const int biq  = __ldg(p_biq);
    const int bikv = __ldg(p_bikv);

    const int lane = tid & 31;
    const int warp = tid >> 5;
    const float scale = 0.08838834764831845f;  // 1/sqrt(128)

    // ---------- Phase A: load + RMS-norm Q,K; load V (swizzled stores) ----------
    {
        const float4 gqv = ((const float4*)(gq + (size_t)h * HD))[lane];
        const float4 gkv = ((const float4*)(gk + (size_t)kvh * HD))[lane];
        const int vslot = ((lane >> 1) | ((lane & 1) << 4));   // V chunk interleave
        for (int r = warp * 16; r < warp * 16 + 16; ++r) {
            // Q row (plain row-major chunks)
            float4 x = ((const float4*)(q + ((size_t)(b * BQ + r) * HQ + h) * HD))[lane];
            float ssq = warp_sum(x.x * x.x + x.y * x.y + x.z * x.z + x.w * x.w);
            float riq = rsqrtf(ssq * (1.0f / HD) + EPSV);
            float4 qv; qv.x = x.x * riq * gqv.x; qv.y = x.y * riq * gqv.y;
                       qv.z = x.z * riq * gqv.z; qv.w = x.w * riq * gqv.w;
            *(float4*)&sQ[r * PITCH + lane * 4] = qv;
            // K row (chunk c stored at slot (c + r>>3) & 31)
            float4 y = ((const float4*)(k + ((size_t)(b * BKV + r) * HKV + kvh) * HD))[lane];
            float ssk = warp_sum(y.x * y.x + y.y * y.y + y.z * y.z + y.w * y.w);
            float rik = rsqrtf(ssk * (1.0f / HD) + EPSV);
            float4 kv2; kv2.x = y.x * rik * gkv.x; kv2.y = y.y * rik * gkv.y;
                        kv2.z = y.z * rik * gkv.z; kv2.w = y.w * rik * gkv.w;
            int kslot = (lane + (r >> 3)) & 31;
            *(float4*)&sK[r * PITCH + kslot * 4] = kv2;
            // V row (chunk c stored at slot (c>>1)|((c&1)<<4))
            float4 z = ((const float4*)(v + ((size_t)(b * BKV + r) * HKV + kvh) * HD))[lane];
            *(float4*)&sV[r * PITCH + vslot * 4] = z;
        }
    }
    __syncthreads();

    const int tr = tid >> 4;    // 0..15
    const int tc = tid & 15;    // 0..15
    const int r0 = tr * 8;
    const int c0 = tc * 8;

    // ---------- GEMM1: S = Qn @ Kn^T (vectorized, swizzled B) ----------
    float acc[8][8];
    #pragma unroll
    for (int i = 0; i < 8; ++i)
        #pragma unroll
        for (int j = 0; j < 8; ++j) acc[i][j] = 0.0f;

    for (int d4 = 0; d4 < 32; ++d4) {
        const int kslot = ((d4 + tc) & 31) * 4;   // rows c0..c0+7 share (row>>3)==tc
        float4 kb[8];
        #pragma unroll
        for (int j = 0; j < 8; ++j)
            kb[j] = *(const float4*)&sK[(c0 + j) * PITCH + kslot];
        #pragma unroll
        for (int i = 0; i < 8; ++i) {
            float4 a = *(const float4*)&sQ[(r0 + i) * PITCH + d4 * 4];
            #pragma unroll
            for (int j = 0; j < 8; ++j) {
                acc[i][j] = fmaf(a.x, kb[j].x, acc[i][j]);
                acc[i][j] = fmaf(a.y, kb[j].y, acc[i][j]);
                acc[i][j] = fmaf(a.z, kb[j].z, acc[i][j]);
                acc[i][j] = fmaf(a.w, kb[j].w, acc[i][j]);
            }
        }
    }
    __syncthreads();   // done reading sQ/sK -> safe to reuse

    // ---------- scale + tanh cap + mask + row max ----------
    float* red = sK;   // reuse as [BQ][RPITCH]
    const int qbase = biq * BQ;
    const int kbase = bikv * BKV;
    const int offs  = SKVC - SQC;
    #pragma unroll
    for (int i = 0; i < 8; ++i) {
        const int qi = qbase + r0 + i;
        float m = -INFINITY;
        #pragma unroll
        for (int j = 0; j < 8; ++j) {
            const int kj = kbase + c0 + j;
            float s = acc[i][j] * scale;
            s = CAPV * tanhf(s * (1.0f / CAPV));
            const bool allowed = (kj <= qi + offs) && (kj >= qi + offs - WIN) &&
                                 (qi < SQC) && (kj < SKVC);
            s = allowed ? s : -INFINITY;
            acc[i][j] = s;
            m = fmaxf(m, s);
        }
        red[(r0 + i) * RPITCH + tc] = m;
    }
    __syncthreads();
    if (tid < BQ) {
        float m = -INFINITY;
        #pragma unroll
        for (int t = 0; t < 16; ++t) m = fmaxf(m, red[tid * RPITCH + t]);
        rowmax_s[tid] = m;
    }
    __syncthreads();

    // ---------- exp (unnormalized), write P, partial sums ----------
    float* sP = sQ;
    #pragma unroll
    for (int i = 0; i < 8; ++i) {
        const float m = rowmax_s[r0 + i];
        float s = 0.0f;
        float4 p0, p1;
        float pv[8];
        #pragma unroll
        for (int j = 0; j < 8; ++j) {
            pv[j] = (m == -INFINITY) ? 0.0f : __expf(acc[i][j] - m);
            s += pv[j];
        }
        p0.x = pv[0]; p0.y = pv[1]; p0.z = pv[2]; p0.w = pv[3];
        p1.x = pv[4]; p1.y = pv[5]; p1.z = pv[6]; p1.w = pv[7];
        *(float4*)&sP[(r0 + i) * PITCH + c0]     = p0;
        *(float4*)&sP[(r0 + i) * PITCH + c0 + 4] = p1;
        red[(r0 + i) * RPITCH + tc] = s;
    }
    __syncthreads();

    // ---------- per-row: lse_blk, merge coefficients, lse write ----------
    if (tid < BQ) {
        float s = 0.0f;
        #pragma unroll
        for (int t = 0; t < 16; ++t) s += red[tid * RPITCH + t];
        const float m = rowmax_s[tid];
        const float lse_blk = (s > 0.0f && m > -INFINITY) ? (m + logf(s)) : -INFINITY;

        const int grow = qbase + tid;
        const float lo = g_lse[((size_t)b * HQ + h) * SQC + grow];
        const float m2 = fmaxf(lo, lse_blk);
        float lnew, co, cb;
        if (m2 == -INFINITY) {
            lnew = -INFINITY; co = 0.0f; cb = 0.0f;
        } else {
            float e0 = (lo == -INFINITY) ? 0.0f : expf(lo - m2);
            float e1 = (lse_blk == -INFINITY) ? 0.0f : expf(lse_blk - m2);
            lnew = m2 + logf(e0 + e1);
            co = (lo == -INFINITY) ? 0.0f : expf(lo - lnew);
            cb = (lse_blk == -INFINITY) ? 0.0f : expf(lse_blk - lnew);
        }
        co_s[tid] = co;
        cb_s[tid] = (s > 0.0f) ? (cb / s) : 0.0f;   // fold 1/rowsum into block coeff
        out_lse[((size_t)b * HQ + h) * SQC + grow] = lnew;
    }
    __syncthreads();

    // ---------- GEMM2: O_blk = P @ V (vectorized, interleaved V) ----------
    float acc2[8][8];
    #pragma unroll
    for (int i = 0; i < 8; ++i)
        #pragma unroll
        for (int j = 0; j < 8; ++j) acc2[i][j] = 0.0f;

    for (int k4 = 0; k4 < 32; ++k4) {
        const int kk = k4 * 4;
        float4 pa[8];
        #pragma unroll
        for (int i = 0; i < 8; ++i)
            pa[i] = *(const float4*)&sP[(r0 + i) * PITCH + kk];
        #pragma unroll
        for (int kl = 0; kl < 4; ++kl) {
            const float4 v0 = *(const float4*)&sV[(kk + kl) * PITCH + tc * 4];
            const float4 v1 = *(const float4*)&sV[(kk + kl) * PITCH + tc * 4 + 64];
            #pragma unroll
            for (int i = 0; i < 8; ++i) {
                const float p = ((const float*)&pa[i])[kl];
                acc2[i][0] = fmaf(p, v0.x, acc2[i][0]);
                acc2[i][1] = fmaf(p, v0.y, acc2[i][1]);
                acc2[i][2] = fmaf(p, v0.z, acc2[i][2]);
                acc2[i][3] = fmaf(p, v0.w, acc2[i][3]);
                acc2[i][4] = fmaf(p, v1.x, acc2[i][4]);
                acc2[i][5] = fmaf(p, v1.y, acc2[i][5]);
                acc2[i][6] = fmaf(p, v1.z, acc2[i][6]);
                acc2[i][7] = fmaf(p, v1.w, acc2[i][7]);
            }
        }
    }

    // ---------- merge with old global O and write (float4) ----------
    #pragma unroll
    for (int i = 0; i < 8; ++i) {
        const int r = r0 + i;
        const int grow = qbase + r;
        const size_t base = (((size_t)b * SQC + grow) * HQ + h) * HD + c0;
        const float co = co_s[r];
        const float cb = cb_s[r];
        float4 g0 = *(const float4*)&g_o[base];
        float4 g1 = *(const float4*)&g_o[base + 4];
        float4 o0, o1;
        o0.x = co * g0.x + cb * acc2[i][0]; o0.y = co * g0.y + cb * acc2[i][1];
        o0.z = co * g0.z + cb * acc2[i][2]; o0.w = co * g0.w + cb * acc2[i][3];
        o1.x = co * g1.x + cb * acc2[i][4]; o1.y = co * g1.y + cb * acc2[i][5];
        o1.z = co * g1.z + cb * acc2[i][6]; o1.w = co * g1.w + cb * acc2[i][7];
        *(float4*)&out_o[base]     = o0;
        *(float4*)&out_o[base + 4] = o1;
    }
}

extern "C" void kernel_launch(void* const* d_in, const int* in_sizes, int n_in,
                              void* d_out, int out_size)
{
    const float* q     = (const float*)d_in[0];
    const float* k     = (const float*)d_in[1];
    const float* v     = (const float*)d_in[2];
    const float* g_o   = (const float*)d_in[3];
    const float* g_lse = (const float*)d_in[4];
    const float* gq    = (const float*)d_in[5];
    const float* gk    = (const float*)d_in[6];
    const int*   biq   = (const int*)d_in[7];
    const int*   bikv  = (const int*)d_in[8];

    float* out = (float*)d_out;

    const int b_dim = in_sizes[0] / (BQ * HQ * HD);                 // 4
    const unsigned long long o_elems   = (unsigned long long)in_sizes[3];
    const unsigned long long lse_elems = (unsigned long long)in_sizes[4];
    const int natt = b_dim * HQ;                                    // 128

    const size_t smem = (size_t)3 * BQ * PITCH * sizeof(float);     // 202752 B
    cudaFuncSetAttribute(oswa_fused,
                         cudaFuncAttributeMaxDynamicSharedMemorySize, (int)smem);

    // One launch: bids [0, natt) = attention CTAs (long jobs first),
    // bids [natt, natt+NCOPY) = copy CTAs that skip the block region.
    oswa_fused<<<natt + NCOPY, 256, smem, 0>>>(
        q, k, v, g_o, g_lse, gq, gk, biq, bikv,
        out, out + o_elems, natt, o_elems, lse_elems);
}